// round 1
// baseline (speedup 1.0000x reference)
#include <cuda_runtime.h>
#include <cuda_bf16.h>
#include <math.h>

// Problem constants
#define Mdim 8192   // B*T = 2*4096
#define Ddim 2048
#define MEM_DECAY 0.01f
#define MEM_LR 0.1f
#define MEM_MOMENTUM 0.9f

// -------------------- scratch (static __device__, no allocation) ------------
__device__ float g_Yk[(size_t)Mdim * Ddim];      // silu(x @ Wk^T)
__device__ float g_Yq[(size_t)Mdim * Ddim];      // silu(x @ Wq^T)
__device__ float g_WnT[(size_t)Ddim * Ddim];     // W_new transposed: WnT[d][e] = W_new[e][d]
__device__ float g_Weff[(size_t)Ddim * Ddim];    // Weff = Wout @ W_new  (row-major [D,D])
__device__ float g_rowinv_k[Mdim];
__device__ float g_rowinv_q[Mdim];
__device__ float g_kmean[Ddim];
__device__ float g_vmean[Ddim];
__device__ float g_alpha[Ddim];
__device__ float g_theta[Ddim];
__device__ float g_eta[Ddim];
__device__ float g_err[Ddim];

// -------------------- helpers ------------------------------------------------
__device__ __forceinline__ float sigmoidf_(float x) { return 1.f / (1.f + __expf(-x)); }
__device__ __forceinline__ float siluf_(float x)    { return x * sigmoidf_(x); }

// -------------------- GEMM: C[m,n] = sum_k A[m,k] * B[n,k] -------------------
// A: [M,K] row-major, B: [N,K] row-major (i.e. computes A @ B^T).
// Tile 128x128, K-step 8, 256 threads, 8x8 per-thread micro-tile.
enum {
    EPI_STORE_SILU = 0,     // C = silu(acc)                         -> C
    EPI_COLSUM_SILU = 1,    // atomicAdd(colsum[n], silu(acc)*scale)
    EPI_COLSUM_SIG = 2,     // atomicAdd(colsum[n], sigmoid(acc+bias[n])*scale)
    EPI_STORE_NONE = 3,     // C = acc
    EPI_STORE_ROWSCALE = 4  // C = acc * rowscale[m]
};

template <int MODE>
__global__ void __launch_bounds__(256)
gemm_kernel(const float* __restrict__ A, const float* __restrict__ Bm,
            float* __restrict__ C, const float* __restrict__ bias,
            float scale, float* __restrict__ colsum,
            const float* __restrict__ rowscale,
            int M, int N, int K)
{
    __shared__ float As[8][128];
    __shared__ float Bs[8][128];

    const int bm = blockIdx.y * 128;
    const int bn = blockIdx.x * 128;
    const int tid = threadIdx.x;
    const int lr = tid >> 1;            // 0..127 row of the load tile
    const int lc = (tid & 1) << 2;      // 0 or 4
    const int tx = tid & 15;
    const int ty = tid >> 4;

    float acc[8][8];
#pragma unroll
    for (int i = 0; i < 8; i++)
#pragma unroll
        for (int j = 0; j < 8; j++) acc[i][j] = 0.f;

    const float* Ab = A + (size_t)(bm + lr) * K + lc;
    const float* Bb = Bm + (size_t)(bn + lr) * K + lc;

    for (int k0 = 0; k0 < K; k0 += 8) {
        float4 a4 = *(const float4*)(Ab + k0);
        float4 b4 = *(const float4*)(Bb + k0);
        As[lc + 0][lr] = a4.x; As[lc + 1][lr] = a4.y;
        As[lc + 2][lr] = a4.z; As[lc + 3][lr] = a4.w;
        Bs[lc + 0][lr] = b4.x; Bs[lc + 1][lr] = b4.y;
        Bs[lc + 2][lr] = b4.z; Bs[lc + 3][lr] = b4.w;
        __syncthreads();
#pragma unroll
        for (int kk = 0; kk < 8; kk++) {
            float4 af0 = *(const float4*)&As[kk][ty * 8];
            float4 af1 = *(const float4*)&As[kk][ty * 8 + 4];
            float4 bf0 = *(const float4*)&Bs[kk][tx * 8];
            float4 bf1 = *(const float4*)&Bs[kk][tx * 8 + 4];
            float a[8] = {af0.x, af0.y, af0.z, af0.w, af1.x, af1.y, af1.z, af1.w};
            float b[8] = {bf0.x, bf0.y, bf0.z, bf0.w, bf1.x, bf1.y, bf1.z, bf1.w};
#pragma unroll
            for (int i = 0; i < 8; i++)
#pragma unroll
                for (int j = 0; j < 8; j++) acc[i][j] += a[i] * b[j];
        }
        __syncthreads();
    }

    // ---------------- epilogue ----------------
    if constexpr (MODE == EPI_STORE_SILU || MODE == EPI_STORE_NONE ||
                  MODE == EPI_STORE_ROWSCALE) {
#pragma unroll
        for (int i = 0; i < 8; i++) {
            const int row = bm + ty * 8 + i;
            float rs = 1.f;
            if constexpr (MODE == EPI_STORE_ROWSCALE) rs = rowscale[row];
            float* cp = C + (size_t)row * N + bn + tx * 8;
            float o[8];
#pragma unroll
            for (int j = 0; j < 8; j++) {
                float v = acc[i][j];
                if constexpr (MODE == EPI_STORE_SILU) v = siluf_(v);
                if constexpr (MODE == EPI_STORE_ROWSCALE) v = v * rs;
                o[j] = v;
            }
            *(float4*)cp       = make_float4(o[0], o[1], o[2], o[3]);
            *(float4*)(cp + 4) = make_float4(o[4], o[5], o[6], o[7]);
        }
    } else {
        float s[8];
#pragma unroll
        for (int j = 0; j < 8; j++) s[j] = 0.f;
        if constexpr (MODE == EPI_COLSUM_SILU) {
#pragma unroll
            for (int i = 0; i < 8; i++)
#pragma unroll
                for (int j = 0; j < 8; j++) s[j] += siluf_(acc[i][j]);
        } else {  // EPI_COLSUM_SIG
            float bj[8];
#pragma unroll
            for (int j = 0; j < 8; j++) bj[j] = bias[bn + tx * 8 + j];
#pragma unroll
            for (int i = 0; i < 8; i++)
#pragma unroll
                for (int j = 0; j < 8; j++) s[j] += sigmoidf_(acc[i][j] + bj[j]);
        }
#pragma unroll
        for (int j = 0; j < 8; j++)
            atomicAdd(&colsum[bn + tx * 8 + j], s[j] * scale);
    }
}

// -------------------- small kernels ------------------------------------------
__global__ void zero_vectors_kernel() {
    int i = blockIdx.x * blockDim.x + threadIdx.x;
    if (i < Ddim) {
        g_kmean[i] = 0.f; g_vmean[i] = 0.f;
        g_alpha[i] = 0.f; g_theta[i] = 0.f; g_eta[i] = 0.f;
    }
}

// per-row 1/max(||row||,1e-12) over Y [M x N]; one warp per row
__global__ void rowinv_kernel(const float* __restrict__ Y, float* __restrict__ rowinv, int N) {
    int row = blockIdx.x * 8 + (threadIdx.x >> 5);
    int lane = threadIdx.x & 31;
    const float4* p = (const float4*)(Y + (size_t)row * N);
    float s = 0.f;
    for (int i = lane; i < N / 4; i += 32) {
        float4 v = p[i];
        s += v.x * v.x + v.y * v.y + v.z * v.z + v.w * v.w;
    }
#pragma unroll
    for (int o = 16; o; o >>= 1) s += __shfl_xor_sync(0xffffffffu, s, o);
    if (lane == 0) rowinv[row] = 1.f / fmaxf(sqrtf(s), 1e-12f);
}

// column sum of Y[m,c]*rowinv[m] * mul, atomically into outv
__global__ void colsum_scaled_kernel(const float* __restrict__ Y,
                                     const float* __restrict__ rowinv,
                                     float* __restrict__ outv,
                                     int M, int N, float mul) {
    int col = blockIdx.x * blockDim.x + threadIdx.x;
    int rows_per = M / gridDim.y;
    int r0 = blockIdx.y * rows_per;
    float s = 0.f;
    for (int r = r0; r < r0 + rows_per; r++) s += Y[(size_t)r * N + col] * rowinv[r];
    atomicAdd(&outv[col], s * mul);
}

// err[e] = dot(state_W[e,:], kmean) - vmean[e] ; one warp per row
__global__ void error_kernel(const float* __restrict__ sW) {
    int e = blockIdx.x * 8 + (threadIdx.x >> 5);
    int lane = threadIdx.x & 31;
    const float4* w = (const float4*)(sW + (size_t)e * Ddim);
    const float4* k4 = (const float4*)g_kmean;
    float s = 0.f;
    for (int i = lane; i < Ddim / 4; i += 32) {
        float4 a = w[i], b = k4[i];
        s += a.x * b.x + a.y * b.y + a.z * b.z + a.w * b.w;
    }
#pragma unroll
    for (int o = 16; o; o >>= 1) s += __shfl_xor_sync(0xffffffffu, s, o);
    if (lane == 0) g_err[e] = s - g_vmean[e];
}

// WnT[d][e] = (1-alpha[e])*sW[e][d] + eta[e]*mom[e][d] - theta[e]*(2/D)*err[e]*kmean[d]
__global__ void wnewT_kernel(const float* __restrict__ sW, const float* __restrict__ sMom) {
    __shared__ float tile[32][33];
    int e = blockIdx.y * 32 + threadIdx.y;
    int d = blockIdx.x * 32 + threadIdx.x;
    float a = g_alpha[e], et = g_eta[e], th = g_theta[e], er = g_err[e];
    float km = g_kmean[d];
    size_t idx = (size_t)e * Ddim + d;
    float val = (1.f - a) * sW[idx] + et * sMom[idx] - th * (2.f / (float)Ddim) * er * km;
    tile[threadIdx.y][threadIdx.x] = val;
    __syncthreads();
    int dt = blockIdx.x * 32 + threadIdx.y;
    int et2 = blockIdx.y * 32 + threadIdx.x;
    g_WnT[(size_t)dt * Ddim + et2] = tile[threadIdx.x][threadIdx.y];
}

// -------------------- launch ---------------------------------------------------
extern "C" void kernel_launch(void* const* d_in, const int* in_sizes, int n_in,
                              void* d_out, int out_size) {
    const float* x   = (const float*)d_in[0];
    const float* sW  = (const float*)d_in[1];
    const float* sM  = (const float*)d_in[2];
    const float* Wk  = (const float*)d_in[3];
    const float* Wv  = (const float*)d_in[4];
    const float* Wq  = (const float*)d_in[5];
    const float* Wout = (const float*)d_in[6];
    const float* Wd  = (const float*)d_in[7];
    const float* bd  = (const float*)d_in[8];
    const float* Wlr = (const float*)d_in[9];
    const float* blr = (const float*)d_in[10];
    const float* Wm  = (const float*)d_in[11];
    const float* bm  = (const float*)d_in[12];
    float* out = (float*)d_out;

    float *p_Yk, *p_Yq, *p_WnT, *p_Weff, *p_rik, *p_riq;
    float *p_kmean, *p_vmean, *p_alpha, *p_theta, *p_eta;
    cudaGetSymbolAddress((void**)&p_Yk, g_Yk);
    cudaGetSymbolAddress((void**)&p_Yq, g_Yq);
    cudaGetSymbolAddress((void**)&p_WnT, g_WnT);
    cudaGetSymbolAddress((void**)&p_Weff, g_Weff);
    cudaGetSymbolAddress((void**)&p_rik, g_rowinv_k);
    cudaGetSymbolAddress((void**)&p_riq, g_rowinv_q);
    cudaGetSymbolAddress((void**)&p_kmean, g_kmean);
    cudaGetSymbolAddress((void**)&p_vmean, g_vmean);
    cudaGetSymbolAddress((void**)&p_alpha, g_alpha);
    cudaGetSymbolAddress((void**)&p_theta, g_theta);
    cudaGetSymbolAddress((void**)&p_eta, g_eta);

    const float invM = 1.f / (float)Mdim;

    // 0) zero accumulators
    zero_vectors_kernel<<<(Ddim + 255) / 256, 256>>>();

    dim3 gBig(Ddim / 128, Mdim / 128);   // 16 x 64
    dim3 gSq(Ddim / 128, Ddim / 128);    // 16 x 16

    // 1) Yk = silu(x @ Wk^T)
    gemm_kernel<EPI_STORE_SILU><<<gBig, 256>>>(x, Wk, p_Yk, nullptr, 0.f, nullptr, nullptr,
                                               Mdim, Ddim, Ddim);
    // 2) Yq = silu(x @ Wq^T)
    gemm_kernel<EPI_STORE_SILU><<<gBig, 256>>>(x, Wq, p_Yq, nullptr, 0.f, nullptr, nullptr,
                                               Mdim, Ddim, Ddim);
    // 3) v_mean
    gemm_kernel<EPI_COLSUM_SILU><<<gBig, 256>>>(x, Wv, nullptr, nullptr, invM, p_vmean, nullptr,
                                                Mdim, Ddim, Ddim);
    // 4-6) gate means: alpha, theta, eta
    gemm_kernel<EPI_COLSUM_SIG><<<gBig, 256>>>(x, Wd, nullptr, bd, MEM_DECAY * invM, p_alpha,
                                               nullptr, Mdim, Ddim, Ddim);
    gemm_kernel<EPI_COLSUM_SIG><<<gBig, 256>>>(x, Wlr, nullptr, blr, MEM_LR * invM, p_theta,
                                               nullptr, Mdim, Ddim, Ddim);
    gemm_kernel<EPI_COLSUM_SIG><<<gBig, 256>>>(x, Wm, nullptr, bm, MEM_MOMENTUM * invM, p_eta,
                                               nullptr, Mdim, Ddim, Ddim);

    // 7) per-row inverse norms for k and q
    rowinv_kernel<<<Mdim / 8, 256>>>(p_Yk, p_rik, Ddim);
    rowinv_kernel<<<Mdim / 8, 256>>>(p_Yq, p_riq, Ddim);

    // 8) k_mean = mean_m Yk[m,:] * rowinv_k[m]
    {
        dim3 g(Ddim / 256, 32);
        colsum_scaled_kernel<<<g, 256>>>(p_Yk, p_rik, p_kmean, Mdim, Ddim, invM);
    }

    // 9) err[e] = state_W[e,:].kmean - vmean[e]
    error_kernel<<<Ddim / 8, 256>>>(sW);

    // 10) W_new^T
    {
        dim3 b(32, 32), g(Ddim / 32, Ddim / 32);
        wnewT_kernel<<<g, b>>>(sW, sM);
    }

    // 11) Weff = Wout @ W_new   (C[i,j] = sum_e Wout[i,e] * WnT[j,e])
    gemm_kernel<EPI_STORE_NONE><<<gSq, 256>>>(Wout, p_WnT, p_Weff, nullptr, 0.f, nullptr, nullptr,
                                              Ddim, Ddim, Ddim);

    // 12) out[m,n] = rowinv_q[m] * sum_d Yq[m,d] * Weff[n,d]
    gemm_kernel<EPI_STORE_ROWSCALE><<<gBig, 256>>>(p_Yq, p_Weff, out, nullptr, 0.f, nullptr,
                                                   p_riq, Mdim, Ddim, Ddim);
}

// round 3
// speedup vs baseline: 4.3271x; 4.3271x over previous
#include <cuda_runtime.h>
#include <cuda_bf16.h>
#include <cstdint>
#include <math.h>

#define Mdim 8192
#define Ddim 2048

// ---------------- scratch (__device__ globals, no allocation) ----------------
__device__ __nv_bfloat16 g_xh[(size_t)Mdim * Ddim];
__device__ __nv_bfloat16 g_xl[(size_t)Mdim * Ddim];
// weights: 0=Wk 1=Wv 2=Wq 3=Wd 4=Wlr 5=Wm 6=Wout
__device__ __nv_bfloat16 g_wh[7 * (size_t)Ddim * Ddim];
__device__ __nv_bfloat16 g_wl[7 * (size_t)Ddim * Ddim];
__device__ __nv_bfloat16 g_wnth[(size_t)Ddim * Ddim];
__device__ __nv_bfloat16 g_wntl[(size_t)Ddim * Ddim];
__device__ __nv_bfloat16 g_weffh[(size_t)Ddim * Ddim];
__device__ __nv_bfloat16 g_weffl[(size_t)Ddim * Ddim];
__device__ __nv_bfloat16 g_ykh[(size_t)Mdim * Ddim];
__device__ __nv_bfloat16 g_yqh[(size_t)Mdim * Ddim];
__device__ __nv_bfloat16 g_yql[(size_t)Mdim * Ddim];
__device__ float g_WnT[(size_t)Ddim * Ddim];
__device__ float g_ssk[Mdim], g_ssq[Mdim], g_rik[Mdim], g_riq[Mdim];
__device__ float g_kmean[Ddim], g_vmean[Ddim], g_alpha[Ddim], g_theta[Ddim],
                 g_eta[Ddim], g_err[Ddim];

// ---------------- helpers ----------------
__device__ __forceinline__ float sigmoidf_(float x) { return 1.f / (1.f + __expf(-x)); }
__device__ __forceinline__ float siluf_(float x)    { return x * sigmoidf_(x); }

__device__ __forceinline__ uint32_t smem_u32(const void* p) {
    uint32_t a;
    asm("{ .reg .u64 t; cvta.to.shared.u64 t, %1; cvt.u32.u64 %0, t; }" : "=r"(a) : "l"(p));
    return a;
}
__device__ __forceinline__ void cp16(uint32_t dst, const void* src) {
    asm volatile("cp.async.cg.shared.global [%0], [%1], 16;"
                 :: "r"(dst), "l"(__cvta_generic_to_global(src)));
}
__device__ __forceinline__ void ldm4(uint32_t* r, uint32_t addr) {
    asm volatile("ldmatrix.sync.aligned.m8n8.x4.shared.b16 {%0,%1,%2,%3}, [%4];"
                 : "=r"(r[0]), "=r"(r[1]), "=r"(r[2]), "=r"(r[3]) : "r"(addr));
}
__device__ __forceinline__ void mma_bf16(float* c, const uint32_t* a, const uint32_t* b) {
    asm volatile(
        "mma.sync.aligned.m16n8k16.row.col.f32.bf16.bf16.f32 "
        "{%0,%1,%2,%3}, {%4,%5,%6,%7}, {%8,%9}, {%0,%1,%2,%3};"
        : "+f"(c[0]), "+f"(c[1]), "+f"(c[2]), "+f"(c[3])
        : "r"(a[0]), "r"(a[1]), "r"(a[2]), "r"(a[3]), "r"(b[0]), "r"(b[1]));
}
__device__ __forceinline__ uint32_t pack2bf(float a, float b) {
    __nv_bfloat16 ha = __float2bfloat16(a), hb = __float2bfloat16(b);
    return (uint32_t)__bfloat16_as_ushort(ha) |
           ((uint32_t)__bfloat16_as_ushort(hb) << 16);
}

// ---------------- GEMM: C[m,n] = sum_k A[m,k]*B[n,k] -------------------------
// Tiles: BM=BN=128, BK=64 (128B rows, SW128 swizzle). 256 threads, 8 warps,
// warp tile 64x32 (2x4 warp grid). mma.m16n8k16 bf16 -> f32 acc.
// SPLIT=true: A=Ah+Al, B=Bh+Bl; 3-term (AhBh + AhBl + AlBh).
enum { M_YK = 0, M_YQ = 1, M_CSILU = 2, M_CSIG = 3, M_SPLIT = 4, M_OUT = 5 };

__device__ __forceinline__ void frag_a(uint32_t* r, uint32_t tb, int kk, int wm,
                                       int mt, int lane) {
    int row = wm * 64 + mt * 16 + (lane & 15);
    uint32_t kb = (uint32_t)kk * 32 + ((lane >> 4) << 4);
    ldm4(r, tb + row * 128 + (kb ^ (uint32_t)((row & 7) << 4)));
}
__device__ __forceinline__ void frag_b(uint32_t* r, uint32_t tb, int kk, int wn,
                                       int lane) {
#pragma unroll
    for (int p = 0; p < 2; p++) {
        int row = wn * 32 + p * 16 + ((lane >> 4) & 1) * 8 + (lane & 7);
        uint32_t kb = (uint32_t)kk * 32 + (((lane >> 3) & 1) << 4);
        ldm4(r + 4 * p, tb + row * 128 + (kb ^ (uint32_t)((row & 7) << 4)));
    }
}

template <int MODE, bool SPLIT, int NSTAGE>
__global__ void __launch_bounds__(256)
mma_gemm(const __nv_bfloat16* __restrict__ Ah, const __nv_bfloat16* __restrict__ Al,
         const __nv_bfloat16* __restrict__ Bh, const __nv_bfloat16* __restrict__ Bl,
         float* __restrict__ Cf,
         __nv_bfloat16* __restrict__ Ch, __nv_bfloat16* __restrict__ Cl,
         const float* __restrict__ bias, float scale, float* __restrict__ colsum,
         const float* __restrict__ rowscale, float* __restrict__ rowsumsq, int K)
{
    extern __shared__ char smem[];
    const int tid = threadIdx.x, lane = tid & 31, warp = tid >> 5;
    const int wm = warp & 1, wn = warp >> 1;
    const int bm = blockIdx.y * 128, bn = blockIdx.x * 128;
    const uint32_t sb = smem_u32(smem);
    constexpr int NT = SPLIT ? 4 : 2;
    constexpr uint32_t TB = 128 * 128;       // one tile = 16KB
    constexpr uint32_t STAGE = NT * TB;
    const int NCH = K >> 6;

    float acc[4][4][4];
#pragma unroll
    for (int i = 0; i < 4; i++)
#pragma unroll
        for (int j = 0; j < 4; j++)
#pragma unroll
            for (int e = 0; e < 4; e++) acc[i][j][e] = 0.f;

    const int lr = tid >> 1, lcb = (tid & 1) * 4;   // loader row / col-16B base

    // ---- pipelined main loop ----
    auto do_load = [&](int ch, int st) {
        const int kc = ch * 64;
        const uint32_t base = sb + st * STAGE;
        const __nv_bfloat16* gAh = Ah + (size_t)(bm + lr) * K + kc + lcb * 8;
        const __nv_bfloat16* gBh = Bh + (size_t)(bn + lr) * K + kc + lcb * 8;
#pragma unroll
        for (int j = 0; j < 4; j++) {
            uint32_t off = (uint32_t)lr * 128 + (lcb + j) * 16;
            uint32_t sw = off ^ ((off >> 3) & 0x70u);
            cp16(base + sw,      gAh + j * 8);
            cp16(base + TB + sw, gBh + j * 8);
            if constexpr (SPLIT) {
                const __nv_bfloat16* gAl = Al + (size_t)(bm + lr) * K + kc + lcb * 8;
                const __nv_bfloat16* gBl = Bl + (size_t)(bn + lr) * K + kc + lcb * 8;
                cp16(base + 2 * TB + sw, gAl + j * 8);
                cp16(base + 3 * TB + sw, gBl + j * 8);
            }
        }
    };

#pragma unroll
    for (int s = 0; s < NSTAGE - 1; s++) {
        do_load(s, s);
        asm volatile("cp.async.commit_group;");
    }

    for (int i = 0; i < NCH; i++) {
        if (i + NSTAGE - 1 < NCH) do_load(i + NSTAGE - 1, (i + NSTAGE - 1) % NSTAGE);
        asm volatile("cp.async.commit_group;");
        asm volatile("cp.async.wait_group %0;" :: "n"(NSTAGE - 1));
        __syncthreads();

        const uint32_t tb = sb + (i % NSTAGE) * STAGE;
#pragma unroll
        for (int kk = 0; kk < 4; kk++) {
            uint32_t bh[8], bl[8];
            frag_b(bh, tb + TB, kk, wn, lane);
            if constexpr (SPLIT) frag_b(bl, tb + 3 * TB, kk, wn, lane);
#pragma unroll
            for (int mt = 0; mt < 4; mt++) {
                uint32_t a[4];
                frag_a(a, tb, kk, wm, mt, lane);
#pragma unroll
                for (int nt = 0; nt < 4; nt++)
                    mma_bf16(acc[mt][nt], a, bh + 2 * nt);
                if constexpr (SPLIT) {
#pragma unroll
                    for (int nt = 0; nt < 4; nt++)
                        mma_bf16(acc[mt][nt], a, bl + 2 * nt);
                    uint32_t a2[4];
                    frag_a(a2, tb + 2 * TB, kk, wm, mt, lane);
#pragma unroll
                    for (int nt = 0; nt < 4; nt++)
                        mma_bf16(acc[mt][nt], a2, bh + 2 * nt);
                }
            }
        }
        __syncthreads();
    }

    // ---- epilogue ----
    const int tr = lane >> 2;
    const int tc = (lane & 3) << 1;

    if constexpr (MODE == M_CSILU || MODE == M_CSIG) {
        float cs[8] = {0, 0, 0, 0, 0, 0, 0, 0};
        float bj[8];
        if constexpr (MODE == M_CSIG) {
#pragma unroll
            for (int nt = 0; nt < 4; nt++) {
                int col = bn + wn * 32 + nt * 8 + tc;
                bj[nt * 2] = bias[col];
                bj[nt * 2 + 1] = bias[col + 1];
            }
        }
#pragma unroll
        for (int mt = 0; mt < 4; mt++)
#pragma unroll
            for (int nt = 0; nt < 4; nt++)
#pragma unroll
                for (int e = 0; e < 4; e++) {
                    float f = acc[mt][nt][e];
                    int j = e & 1;
                    float val;
                    if constexpr (MODE == M_CSILU) val = siluf_(f);
                    else                           val = sigmoidf_(f + bj[nt * 2 + j]);
                    cs[nt * 2 + j] += val;
                }
#pragma unroll
        for (int o = 4; o <= 16; o <<= 1)
#pragma unroll
            for (int q = 0; q < 8; q++)
                cs[q] += __shfl_xor_sync(0xffffffffu, cs[q], o);
        if (tr == 0) {
#pragma unroll
            for (int nt = 0; nt < 4; nt++) {
                int col = bn + wn * 32 + nt * 8 + tc;
                atomicAdd(&colsum[col],     cs[nt * 2]     * scale);
                atomicAdd(&colsum[col + 1], cs[nt * 2 + 1] * scale);
            }
        }
    } else {
        float rss[8] = {0, 0, 0, 0, 0, 0, 0, 0};
#pragma unroll
        for (int mt = 0; mt < 4; mt++) {
#pragma unroll
            for (int half = 0; half < 2; half++) {
                int row = bm + wm * 64 + mt * 16 + tr + half * 8;
                float rsc = 1.f;
                if constexpr (MODE == M_OUT) rsc = rowscale[row];
#pragma unroll
                for (int nt = 0; nt < 4; nt++) {
                    int col = bn + wn * 32 + nt * 8 + tc;
                    float v0 = acc[mt][nt][half * 2 + 0];
                    float v1 = acc[mt][nt][half * 2 + 1];
                    if constexpr (MODE == M_YK || MODE == M_YQ) {
                        v0 = siluf_(v0); v1 = siluf_(v1);
                        rss[mt * 2 + half] += v0 * v0 + v1 * v1;
                    }
                    if constexpr (MODE == M_OUT) {
                        float2 o = make_float2(v0 * rsc, v1 * rsc);
                        *(float2*)(Cf + (size_t)row * Ddim + col) = o;
                    } else if constexpr (MODE == M_YK) {
                        *(uint32_t*)(Ch + (size_t)row * Ddim + col) = pack2bf(v0, v1);
                    } else {  // M_YQ / M_SPLIT: hi/lo split store
                        __nv_bfloat16 h0 = __float2bfloat16(v0);
                        __nv_bfloat16 h1 = __float2bfloat16(v1);
                        float l0 = v0 - __bfloat162float(h0);
                        float l1 = v1 - __bfloat162float(h1);
                        *(uint32_t*)(Ch + (size_t)row * Ddim + col) =
                            (uint32_t)__bfloat16_as_ushort(h0) |
                            ((uint32_t)__bfloat16_as_ushort(h1) << 16);
                        *(uint32_t*)(Cl + (size_t)row * Ddim + col) = pack2bf(l0, l1);
                    }
                }
            }
        }
        if constexpr (MODE == M_YK || MODE == M_YQ) {
#pragma unroll
            for (int o = 1; o <= 2; o <<= 1)
#pragma unroll
                for (int q = 0; q < 8; q++)
                    rss[q] += __shfl_xor_sync(0xffffffffu, rss[q], o);
            if ((lane & 3) == 0) {
#pragma unroll
                for (int mt = 0; mt < 4; mt++)
#pragma unroll
                    for (int half = 0; half < 2; half++) {
                        int row = bm + wm * 64 + mt * 16 + tr + half * 8;
                        atomicAdd(&rowsumsq[row], rss[mt * 2 + half]);
                    }
            }
        }
    }
}

// ---------------- small kernels ----------------
__global__ void split_kernel(const float* __restrict__ s,
                             __nv_bfloat16* __restrict__ h,
                             __nv_bfloat16* __restrict__ l, int n4) {
    int i = blockIdx.x * blockDim.x + threadIdx.x;
    if (i >= n4) return;
    float4 v = ((const float4*)s)[i];
    __nv_bfloat16 h0 = __float2bfloat16(v.x), h1 = __float2bfloat16(v.y);
    __nv_bfloat16 h2 = __float2bfloat16(v.z), h3 = __float2bfloat16(v.w);
    float l0 = v.x - __bfloat162float(h0), l1 = v.y - __bfloat162float(h1);
    float l2 = v.z - __bfloat162float(h2), l3 = v.w - __bfloat162float(h3);
    uint2 hp, lp;
    hp.x = (uint32_t)__bfloat16_as_ushort(h0) | ((uint32_t)__bfloat16_as_ushort(h1) << 16);
    hp.y = (uint32_t)__bfloat16_as_ushort(h2) | ((uint32_t)__bfloat16_as_ushort(h3) << 16);
    lp.x = pack2bf(l0, l1);
    lp.y = pack2bf(l2, l3);
    ((uint2*)h)[i] = hp;
    ((uint2*)l)[i] = lp;
}

__global__ void zero_kernel() {
    int i = blockIdx.x * blockDim.x + threadIdx.x;
    if (i < Ddim) {
        g_kmean[i] = 0.f; g_vmean[i] = 0.f;
        g_alpha[i] = 0.f; g_theta[i] = 0.f; g_eta[i] = 0.f;
    }
    if (i < Mdim) { g_ssk[i] = 0.f; g_ssq[i] = 0.f; }
}

__global__ void rinv_kernel(const float* __restrict__ ss, float* __restrict__ ri) {
    int i = blockIdx.x * blockDim.x + threadIdx.x;
    if (i < Mdim) ri[i] = 1.f / fmaxf(sqrtf(ss[i]), 1e-12f);
}

// column mean of Y[m,c]*rowinv[m] (Y bf16), atomically into outv
__global__ void colsum_scaled_bf16(const __nv_bfloat16* __restrict__ Y,
                                   const float* __restrict__ rowinv,
                                   float* __restrict__ outv,
                                   int M, int N, float mul) {
    int col = blockIdx.x * blockDim.x + threadIdx.x;
    int rows_per = M / gridDim.y;
    int r0 = blockIdx.y * rows_per;
    float s = 0.f;
    for (int r = r0; r < r0 + rows_per; r++)
        s += __bfloat162float(Y[(size_t)r * N + col]) * rowinv[r];
    atomicAdd(&outv[col], s * mul);
}

// err[e] = dot(state_W[e,:], kmean) - vmean[e]
__global__ void error_kernel(const float* __restrict__ sW) {
    int e = blockIdx.x * 8 + (threadIdx.x >> 5);
    int lane = threadIdx.x & 31;
    const float4* w = (const float4*)(sW + (size_t)e * Ddim);
    const float4* k4 = (const float4*)g_kmean;
    float s = 0.f;
    for (int i = lane; i < Ddim / 4; i += 32) {
        float4 a = w[i], b = k4[i];
        s += a.x * b.x + a.y * b.y + a.z * b.z + a.w * b.w;
    }
#pragma unroll
    for (int o = 16; o; o >>= 1) s += __shfl_xor_sync(0xffffffffu, s, o);
    if (lane == 0) g_err[e] = s - g_vmean[e];
}

// WnT[d][e] = (1-alpha[e])*sW[e][d] + eta[e]*mom[e][d] - theta[e]*(2/D)*err[e]*kmean[d]
__global__ void wnewT_kernel(const float* __restrict__ sW, const float* __restrict__ sMom) {
    __shared__ float tile[32][33];
    int e = blockIdx.y * 32 + threadIdx.y;
    int d = blockIdx.x * 32 + threadIdx.x;
    float a = g_alpha[e], et = g_eta[e], th = g_theta[e], er = g_err[e];
    float km = g_kmean[d];
    size_t idx = (size_t)e * Ddim + d;
    float val = (1.f - a) * sW[idx] + et * sMom[idx]
              - th * (2.f / (float)Ddim) * er * km;
    tile[threadIdx.y][threadIdx.x] = val;
    __syncthreads();
    int dt = blockIdx.x * 32 + threadIdx.y;
    int et2 = blockIdx.y * 32 + threadIdx.x;
    g_WnT[(size_t)dt * Ddim + et2] = tile[threadIdx.x][threadIdx.y];
}

// ---------------- launch ----------------
extern "C" void kernel_launch(void* const* d_in, const int* in_sizes, int n_in,
                              void* d_out, int out_size) {
    const float* x    = (const float*)d_in[0];
    const float* sW   = (const float*)d_in[1];
    const float* sM   = (const float*)d_in[2];
    const float* Wk   = (const float*)d_in[3];
    const float* Wv   = (const float*)d_in[4];
    const float* Wq   = (const float*)d_in[5];
    const float* Wout = (const float*)d_in[6];
    const float* Wd   = (const float*)d_in[7];
    const float* bd   = (const float*)d_in[8];
    const float* Wlr  = (const float*)d_in[9];
    const float* blr  = (const float*)d_in[10];
    const float* Wm   = (const float*)d_in[11];
    const float* bmb  = (const float*)d_in[12];
    float* out = (float*)d_out;

    __nv_bfloat16 *p_xh, *p_xl, *p_wh, *p_wl, *p_wnth, *p_wntl,
                  *p_weffh, *p_weffl, *p_ykh, *p_yqh, *p_yql;
    float *p_WnT, *p_ssk, *p_ssq, *p_rik, *p_riq;
    float *p_kmean, *p_vmean, *p_alpha, *p_theta, *p_eta;
    cudaGetSymbolAddress((void**)&p_xh, g_xh);
    cudaGetSymbolAddress((void**)&p_xl, g_xl);
    cudaGetSymbolAddress((void**)&p_wh, g_wh);
    cudaGetSymbolAddress((void**)&p_wl, g_wl);
    cudaGetSymbolAddress((void**)&p_wnth, g_wnth);
    cudaGetSymbolAddress((void**)&p_wntl, g_wntl);
    cudaGetSymbolAddress((void**)&p_weffh, g_weffh);
    cudaGetSymbolAddress((void**)&p_weffl, g_weffl);
    cudaGetSymbolAddress((void**)&p_ykh, g_ykh);
    cudaGetSymbolAddress((void**)&p_yqh, g_yqh);
    cudaGetSymbolAddress((void**)&p_yql, g_yql);
    cudaGetSymbolAddress((void**)&p_WnT, g_WnT);
    cudaGetSymbolAddress((void**)&p_ssk, g_ssk);
    cudaGetSymbolAddress((void**)&p_ssq, g_ssq);
    cudaGetSymbolAddress((void**)&p_rik, g_rik);
    cudaGetSymbolAddress((void**)&p_riq, g_riq);
    cudaGetSymbolAddress((void**)&p_kmean, g_kmean);
    cudaGetSymbolAddress((void**)&p_vmean, g_vmean);
    cudaGetSymbolAddress((void**)&p_alpha, g_alpha);
    cudaGetSymbolAddress((void**)&p_theta, g_theta);
    cudaGetSymbolAddress((void**)&p_eta, g_eta);

    const int SMEM_SINGLE = 3 * 2 * 16384;   // 98304
    const int SMEM_SPLIT  = 2 * 4 * 16384;   // 131072
    cudaFuncSetAttribute(mma_gemm<M_YK, false, 3>,
                         cudaFuncAttributeMaxDynamicSharedMemorySize, SMEM_SINGLE);
    cudaFuncSetAttribute(mma_gemm<M_CSILU, false, 3>,
                         cudaFuncAttributeMaxDynamicSharedMemorySize, SMEM_SINGLE);
    cudaFuncSetAttribute(mma_gemm<M_CSIG, false, 3>,
                         cudaFuncAttributeMaxDynamicSharedMemorySize, SMEM_SINGLE);
    cudaFuncSetAttribute(mma_gemm<M_YQ, true, 2>,
                         cudaFuncAttributeMaxDynamicSharedMemorySize, SMEM_SPLIT);
    cudaFuncSetAttribute(mma_gemm<M_SPLIT, true, 2>,
                         cudaFuncAttributeMaxDynamicSharedMemorySize, SMEM_SPLIT);
    cudaFuncSetAttribute(mma_gemm<M_OUT, true, 2>,
                         cudaFuncAttributeMaxDynamicSharedMemorySize, SMEM_SPLIT);

    const float invM = 1.f / (float)Mdim;
    const size_t ddd = (size_t)Ddim * Ddim;

    // input conversions / splits
    {
        int n4x = (Mdim * Ddim) / 4;
        split_kernel<<<(n4x + 255) / 256, 256>>>(x, p_xh, p_xl, n4x);
        int n4w = (int)(ddd / 4);
        split_kernel<<<(n4w + 255) / 256, 256>>>(Wk,   p_wh + 0 * ddd, p_wl + 0 * ddd, n4w);
        split_kernel<<<(n4w + 255) / 256, 256>>>(Wv,   p_wh + 1 * ddd, p_wl + 1 * ddd, n4w);
        split_kernel<<<(n4w + 255) / 256, 256>>>(Wq,   p_wh + 2 * ddd, p_wl + 2 * ddd, n4w);
        split_kernel<<<(n4w + 255) / 256, 256>>>(Wd,   p_wh + 3 * ddd, p_wl + 3 * ddd, n4w);
        split_kernel<<<(n4w + 255) / 256, 256>>>(Wlr,  p_wh + 4 * ddd, p_wl + 4 * ddd, n4w);
        split_kernel<<<(n4w + 255) / 256, 256>>>(Wm,   p_wh + 5 * ddd, p_wl + 5 * ddd, n4w);
        split_kernel<<<(n4w + 255) / 256, 256>>>(Wout, p_wh + 6 * ddd, p_wl + 6 * ddd, n4w);
    }
    zero_kernel<<<Mdim / 256, 256>>>();

    dim3 gBig(Ddim / 128, Mdim / 128);   // 16 x 64
    dim3 gSq(Ddim / 128, Ddim / 128);    // 16 x 16

    // Yk = silu(x@Wk^T) -> bf16 + row sumsq (single pass)
    mma_gemm<M_YK, false, 3><<<gBig, 256, SMEM_SINGLE>>>(
        p_xh, nullptr, p_wh + 0 * ddd, nullptr,
        nullptr, p_ykh, nullptr, nullptr, 0.f, nullptr, nullptr, p_ssk, Ddim);
    // v_mean (single pass)
    mma_gemm<M_CSILU, false, 3><<<gBig, 256, SMEM_SINGLE>>>(
        p_xh, nullptr, p_wh + 1 * ddd, nullptr,
        nullptr, nullptr, nullptr, nullptr, invM, p_vmean, nullptr, nullptr, Ddim);
    // gate means (single pass)
    mma_gemm<M_CSIG, false, 3><<<gBig, 256, SMEM_SINGLE>>>(
        p_xh, nullptr, p_wh + 3 * ddd, nullptr,
        nullptr, nullptr, nullptr, bd, 0.01f * invM, p_alpha, nullptr, nullptr, Ddim);
    mma_gemm<M_CSIG, false, 3><<<gBig, 256, SMEM_SINGLE>>>(
        p_xh, nullptr, p_wh + 4 * ddd, nullptr,
        nullptr, nullptr, nullptr, blr, 0.1f * invM, p_theta, nullptr, nullptr, Ddim);
    mma_gemm<M_CSIG, false, 3><<<gBig, 256, SMEM_SINGLE>>>(
        p_xh, nullptr, p_wh + 5 * ddd, nullptr,
        nullptr, nullptr, nullptr, bmb, 0.9f * invM, p_eta, nullptr, nullptr, Ddim);
    // Yq = silu(x@Wq^T) -> hi/lo split + row sumsq (3-term)
    mma_gemm<M_YQ, true, 2><<<gBig, 256, SMEM_SPLIT>>>(
        p_xh, p_xl, p_wh + 2 * ddd, p_wl + 2 * ddd,
        nullptr, p_yqh, p_yql, nullptr, 0.f, nullptr, nullptr, p_ssq, Ddim);

    // row inverse norms
    rinv_kernel<<<Mdim / 256, 256>>>(p_ssk, p_rik);
    rinv_kernel<<<Mdim / 256, 256>>>(p_ssq, p_riq);

    // k_mean
    {
        dim3 g(Ddim / 256, 32);
        colsum_scaled_bf16<<<g, 256>>>(p_ykh, p_rik, p_kmean, Mdim, Ddim, invM);
    }
    error_kernel<<<Ddim / 8, 256>>>(sW);
    {
        dim3 b(32, 32), g(Ddim / 32, Ddim / 32);
        wnewT_kernel<<<g, b>>>(sW, sM);
    }
    // split WnT
    {
        int n4w = (int)(ddd / 4);
        split_kernel<<<(n4w + 255) / 256, 256>>>(p_WnT, p_wnth, p_wntl, n4w);
    }
    // Weff = Wout @ W_new  (3-term), hi/lo split store
    mma_gemm<M_SPLIT, true, 2><<<gSq, 256, SMEM_SPLIT>>>(
        p_wh + 6 * ddd, p_wl + 6 * ddd, p_wnth, p_wntl,
        nullptr, p_weffh, p_weffl, nullptr, 0.f, nullptr, nullptr, nullptr, Ddim);
    // out = rowinv_q * (Yq @ Weff^T)  (3-term)
    mma_gemm<M_OUT, true, 2><<<gBig, 256, SMEM_SPLIT>>>(
        p_yqh, p_yql, p_weffh, p_weffl,
        out, nullptr, nullptr, nullptr, 0.f, nullptr, p_riq, nullptr, Ddim);
}